// round 4
// baseline (speedup 1.0000x reference)
#include <cuda_runtime.h>

// MaxPool2d k=2 s=2 valid, (32,64,224,224) fp32 -> (32,64,112,112).
// Pure HBM stream: 411 MB read + 103 MB write, zero reuse.
// R3: each thread computes a 2x4 output patch (2 output rows x 4 cols):
//   - 8 front-batched LDG.128 from 4 consecutive input rows (MLP=8)
//   - 2 STG.128 to 2 consecutive output rows
//   - streaming cache hints (evict-first) since nothing is ever re-read.
// All accesses 16B-aligned: IW=224 floats (896 B), OW=112 floats (448 B),
// plane strides 16B-divisible.

#define NC_TOTAL   2048              // 32 * 64
#define IH         224
#define IW         224
#define OH         112
#define OW         112
#define IN_PLANE   (IH * IW)         // 50176
#define OUT_PLANE  (OH * OW)         // 12544
#define GROUPS_W   (OW / 4)          // 28 float4 groups per output row
#define ROWPAIRS   (OH / 2)          // 56 output-row pairs
#define TOTAL_THREADS (NC_TOTAL * ROWPAIRS * GROUPS_W)   // 3,211,264

__device__ __forceinline__ float4 ldcs4(const float4* p) {
    return __ldcs(p);
}

__global__ __launch_bounds__(256)
void maxpool2d_k2s2_x2_kernel(const float* __restrict__ in, float* __restrict__ out) {
    int idx = blockIdx.x * blockDim.x + threadIdx.x;
    if (idx >= TOTAL_THREADS) return;

    int w8  = idx % GROUPS_W;            // output col group (4 cols -> 8 input cols)
    int t   = idx / GROUPS_W;
    int ohp = t % ROWPAIRS;              // which pair of output rows
    int nc  = t / ROWPAIRS;

    // Input rows 4*ohp .. 4*ohp+3, cols [w8*8, w8*8+8)
    const float4* r0 = reinterpret_cast<const float4*>(
        in + (size_t)nc * IN_PLANE + (size_t)(ohp * 4) * IW) + w8 * 2;
    const float4* r1 = r0 + (IW / 4);
    const float4* r2 = r1 + (IW / 4);
    const float4* r3 = r2 + (IW / 4);

    // Front-batch all 8 independent 128-bit streaming loads.
    float4 a0 = ldcs4(r0 + 0);
    float4 a1 = ldcs4(r0 + 1);
    float4 b0 = ldcs4(r1 + 0);
    float4 b1 = ldcs4(r1 + 1);
    float4 c0 = ldcs4(r2 + 0);
    float4 c1 = ldcs4(r2 + 1);
    float4 d0 = ldcs4(r3 + 0);
    float4 d1 = ldcs4(r3 + 1);

    float4 o0, o1;
    o0.x = fmaxf(fmaxf(a0.x, a0.y), fmaxf(b0.x, b0.y));
    o0.y = fmaxf(fmaxf(a0.z, a0.w), fmaxf(b0.z, b0.w));
    o0.z = fmaxf(fmaxf(a1.x, a1.y), fmaxf(b1.x, b1.y));
    o0.w = fmaxf(fmaxf(a1.z, a1.w), fmaxf(b1.z, b1.w));

    o1.x = fmaxf(fmaxf(c0.x, c0.y), fmaxf(d0.x, d0.y));
    o1.y = fmaxf(fmaxf(c0.z, c0.w), fmaxf(d0.z, d0.w));
    o1.z = fmaxf(fmaxf(c1.x, c1.y), fmaxf(d1.x, d1.y));
    o1.w = fmaxf(fmaxf(c1.z, c1.w), fmaxf(d1.z, d1.w));

    float4* orow0 = reinterpret_cast<float4*>(
        out + (size_t)nc * OUT_PLANE + (size_t)(ohp * 2) * OW) + w8;
    float4* orow1 = orow0 + (OW / 4);

    __stcs(orow0, o0);
    __stcs(orow1, o1);
}

extern "C" void kernel_launch(void* const* d_in, const int* in_sizes, int n_in,
                              void* d_out, int out_size) {
    const float* in = (const float*)d_in[0];
    float* out = (float*)d_out;
    int blocks = (TOTAL_THREADS + 255) / 256;   // 12544
    maxpool2d_k2s2_x2_kernel<<<blocks, 256>>>(in, out);
}